// round 4
// baseline (speedup 1.0000x reference)
#include <cuda_runtime.h>

// Depthwise separable 4x4 blur, filter [1,3,3,1] (x) [1,3,3,1] / 64.
// Input  (8, 256, 64, 512) fp32, W-pad circular(1), H-pad reflect(1).
// Output (8, 256, 63, 511) fp32.
//
// R4: R3's 4-deep register prefetch ring (read path) + smem-staged,
// alignment-shifted STG.128 store path (store wavefronts 16 -> 4 per
// warp-row). Output rows are 511 floats so the flat row base is misaligned
// by sh = base mod 4 floats; the row is staged in smem shifted by sh so the
// copy-out is one aligned LDS.128 + STG.128 per thread.

#define W   512
#define H   64
#define OW  511
#define OH  63

__device__ __forceinline__ float4 f4_vblur(const float4& a, const float4& b,
                                           const float4& c, const float4& d)
{
    float4 r;
    r.x = ((a.x + d.x) + 3.0f * (b.x + c.x)) * (1.0f / 64.0f);
    r.y = ((a.y + d.y) + 3.0f * (b.y + c.y)) * (1.0f / 64.0f);
    r.z = ((a.z + d.z) + 3.0f * (b.z + c.z)) * (1.0f / 64.0f);
    r.w = ((a.w + d.w) + 3.0f * (b.w + c.w)) * (1.0f / 64.0f);
    return r;
}

__device__ __forceinline__ float4 f4_hblur(const float4& A, const float4& B)
{
    // outputs ox = 4t+1..4t+4 from src cols A=[4t..4t+3], B=[4t+4..4t+7]
    float4 r;
    r.x = (A.x + A.w) + 3.0f * (A.y + A.z);
    r.y = (A.y + B.x) + 3.0f * (A.z + A.w);
    r.z = (A.z + B.y) + 3.0f * (A.w + B.x);
    r.w = (A.w + B.z) + 3.0f * (B.x + B.y);
    return r;
}

__global__ __launch_bounds__(128) void Blur_49976239456711_kernel(
    const float* __restrict__ in, float* __restrict__ out)
{
    const int t   = threadIdx.x;           // 0..127, owns src cols 4t..4t+3
    const int img = blockIdx.x;            // 0..2047

    const float* __restrict__ src = in + (size_t)img * (H * W);
    const int imgbase = img * (OH * OW);   // flat float index of image output

    const int cA = 4 * t;
    const int cB = (4 * t + 4) & (W - 1);  // wraps 512 -> 0 for t=127

    const int ox0  = 4 * t + 1;
    const bool full = (t < 127);           // t=127 covers ox 509,510,(skip),0

    // Double-buffered output row staging. 520 floats/slot (>= 514 needed),
    // 2080 B per slot keeps float4 alignment for both slots.
    __shared__ __align__(16) float buf[2][520];

    auto staged_store = [&](int oy, const float4& v) {
        float* b = buf[oy & 1];
        const int base = imgbase + oy * OW;   // flat float index of row start
        const int sh   = base & 3;            // misalignment in floats

        // Stage row (shifted by sh): smem[sh + ox] <-> flat (base - sh) + sh + ox
        b[sh + ox0]     = v.x;
        b[sh + ox0 + 1] = v.y;
        if (full) {
            b[sh + ox0 + 2] = v.z;
            b[sh + ox0 + 3] = v.w;
        } else {
            b[sh + 0] = v.w;                  // circular wrap: ox=0
        }
        __syncthreads();

        // Copy out: 127 aligned quads + 3 head/tail scalars.
        const int qb = (sh == 0) ? 0 : 4;     // first full quad position in smem
        if (t < 127) {
            const float4 q = *reinterpret_cast<const float4*>(b + qb + 4 * t);
            *reinterpret_cast<float4*>(out + (base - sh) + qb + 4 * t) = q;
        } else if (sh == 0) {
            out[base + 508] = b[508];
            out[base + 509] = b[509];
            out[base + 510] = b[510];
        } else {
            #pragma unroll
            for (int i = 0; i < 3; ++i)        // head: ox 0 .. 3-sh
                if (i < 4 - sh) out[base + i] = b[sh + i];
            #pragma unroll
            for (int j = 0; j < 2; ++j)        // tail: ox 512-sh .. 510
                if (j < sh - 1) out[base + 512 - sh + j] = b[512 + j];
        }
    };

    // ── 4-deep prefetch ring: slot s holds src row (loaded 4 iters ahead) ──
    float4 pa[4], pb[4];

    auto issue = [&](int y, int s) {
        pa[s] = __ldg(reinterpret_cast<const float4*>(src + y * W + cA));
        pb[s] = __ldg(reinterpret_cast<const float4*>(src + y * W + cB));
    };

    // Prologue: prefetch rows 2..5 (consumed at oy = 0..3), plus rows 1,0 for
    // the initial window (reflect: padded 0->src 1, padded 1->src 0, padded 2->src 1).
    issue(2, 0); issue(3, 1); issue(4, 2); issue(5, 3);

    const float4 A1 = __ldg(reinterpret_cast<const float4*>(src + 1 * W + cA));
    const float4 B1 = __ldg(reinterpret_cast<const float4*>(src + 1 * W + cB));
    const float4 A0 = __ldg(reinterpret_cast<const float4*>(src + 0 * W + cA));
    const float4 B0 = __ldg(reinterpret_cast<const float4*>(src + 0 * W + cB));

    float4 hb0 = f4_hblur(A1, B1);   // HB[padded 0] = src row 1
    float4 hb1 = f4_hblur(A0, B0);   // HB[padded 1] = src row 0
    float4 hb2 = hb0;                // HB[padded 2] = src row 1
    float4 hb3;

    // Main loop: output oy consumes src row oy+2 from slot (oy&3), refills
    // that slot with src row oy+6 (issued before the barrier so loads stay
    // in flight across it).
    #pragma unroll 2
    for (int oy = 0; oy < OH - 1; ++oy) {          // oy = 0..61
        const int s = oy & 3;
        hb3 = f4_hblur(pa[s], pb[s]);              // src row oy+2
        const int ny = oy + 6;
        if (ny < H) issue(ny, s);
        staged_store(oy, f4_vblur(hb0, hb1, hb2, hb3));
        hb0 = hb1; hb1 = hb2; hb2 = hb3;
    }

    // oy = 62: padded row 65 reflects to src row 62 (hot in cache — reload)
    {
        const float4 A = __ldg(reinterpret_cast<const float4*>(src + 62 * W + cA));
        const float4 B = __ldg(reinterpret_cast<const float4*>(src + 62 * W + cB));
        hb3 = f4_hblur(A, B);
        staged_store(OH - 1, f4_vblur(hb0, hb1, hb2, hb3));
    }
}

extern "C" void kernel_launch(void* const* d_in, const int* in_sizes, int n_in,
                              void* d_out, int out_size)
{
    const float* h = (const float*)d_in[0];
    float* out = (float*)d_out;

    const int n_img = 8 * 256;              // 2048 images of 64x512
    Blur_49976239456711_kernel<<<n_img, 128>>>(h, out);
}

// round 5
// speedup vs baseline: 1.3296x; 1.3296x over previous
#include <cuda_runtime.h>

// Depthwise separable 4x4 blur, filter [1,3,3,1] (x) [1,3,3,1] / 64.
// Input  (8, 256, 64, 512) fp32, W-pad circular(1), H-pad reflect(1).
// Output (8, 256, 63, 511) fp32.
//
// R5: R3's 4-deep register prefetch ring (unroll 4 -> static ring indices,
// regs not local mem) + smem-staged alignment-shifted STG.128 store path
// (store wavefronts 16 -> 4 per warp-row). R4's regression was unroll 2
// making the ring index dynamic -> local-memory spill; this restores it.

#define W   512
#define H   64
#define OW  511
#define OH  63

__device__ __forceinline__ float4 f4_vblur(const float4& a, const float4& b,
                                           const float4& c, const float4& d)
{
    float4 r;
    r.x = ((a.x + d.x) + 3.0f * (b.x + c.x)) * (1.0f / 64.0f);
    r.y = ((a.y + d.y) + 3.0f * (b.y + c.y)) * (1.0f / 64.0f);
    r.z = ((a.z + d.z) + 3.0f * (b.z + c.z)) * (1.0f / 64.0f);
    r.w = ((a.w + d.w) + 3.0f * (b.w + c.w)) * (1.0f / 64.0f);
    return r;
}

__device__ __forceinline__ float4 f4_hblur(const float4& A, const float4& B)
{
    // outputs ox = 4t+1..4t+4 from src cols A=[4t..4t+3], B=[4t+4..4t+7]
    float4 r;
    r.x = (A.x + A.w) + 3.0f * (A.y + A.z);
    r.y = (A.y + B.x) + 3.0f * (A.z + A.w);
    r.z = (A.z + B.y) + 3.0f * (A.w + B.x);
    r.w = (A.w + B.z) + 3.0f * (B.x + B.y);
    return r;
}

__global__ __launch_bounds__(128) void Blur_49976239456711_kernel(
    const float* __restrict__ in, float* __restrict__ out)
{
    const int t   = threadIdx.x;           // 0..127, owns src cols 4t..4t+3
    const int img = blockIdx.x;            // 0..2047

    const float* __restrict__ src = in + (size_t)img * (H * W);
    const int imgbase = img * (OH * OW);   // flat float index of image output

    const int cA = 4 * t;
    const int cB = (4 * t + 4) & (W - 1);  // wraps 512 -> 0 for t=127

    const int ox0  = 4 * t + 1;
    const bool full = (t < 127);           // t=127 covers ox 509,510,(skip),0

    // Double-buffered output row staging. 520 floats/slot keeps float4
    // alignment for both slots (>= 514 floats needed per row incl. shift).
    __shared__ __align__(16) float buf[2][520];

    auto staged_store = [&](int oy, const float4& v) {
        float* b = buf[oy & 1];
        const int base = imgbase + oy * OW;   // flat float index of row start
        const int sh   = base & 3;            // misalignment in floats

        // Stage row shifted by sh: smem[sh + ox] <-> flat (base - sh) + sh + ox
        b[sh + ox0]     = v.x;
        b[sh + ox0 + 1] = v.y;
        if (full) {
            b[sh + ox0 + 2] = v.z;
            b[sh + ox0 + 3] = v.w;
        } else {
            b[sh + 0] = v.w;                  // circular wrap: ox=0
        }
        __syncthreads();

        // Copy out: 127 aligned LDS.128+STG.128 quads + 3 head/tail scalars.
        const int qb = (sh == 0) ? 0 : 4;     // first full quad position
        if (t < 127) {
            const float4 q = *reinterpret_cast<const float4*>(b + qb + 4 * t);
            *reinterpret_cast<float4*>(out + (base - sh) + qb + 4 * t) = q;
        } else if (sh == 0) {
            out[base + 508] = b[508];
            out[base + 509] = b[509];
            out[base + 510] = b[510];
        } else {
            #pragma unroll
            for (int i = 0; i < 3; ++i)        // head: ox 0 .. 3-sh
                if (i < 4 - sh) out[base + i] = b[sh + i];
            #pragma unroll
            for (int j = 0; j < 2; ++j)        // tail: ox 512-sh .. 510
                if (j < sh - 1) out[base + 512 - sh + j] = b[512 + j];
        }
        // No trailing sync needed: next iteration writes the OTHER slot, and
        // its own __syncthreads orders slot reuse two iterations out.
    };

    // ── 4-deep prefetch ring: slot s holds src row (loaded 4 iters ahead) ──
    float4 pa[4], pb[4];

    auto issue = [&](int y, int s) {
        pa[s] = __ldg(reinterpret_cast<const float4*>(src + y * W + cA));
        pb[s] = __ldg(reinterpret_cast<const float4*>(src + y * W + cB));
    };

    // Prologue: prefetch rows 2..5 (consumed at oy = 0..3), plus rows 1,0 for
    // the initial window (reflect: padded 0->src 1, padded 1->src 0, padded 2->src 1).
    issue(2, 0); issue(3, 1); issue(4, 2); issue(5, 3);

    const float4 A1 = __ldg(reinterpret_cast<const float4*>(src + 1 * W + cA));
    const float4 B1 = __ldg(reinterpret_cast<const float4*>(src + 1 * W + cB));
    const float4 A0 = __ldg(reinterpret_cast<const float4*>(src + 0 * W + cA));
    const float4 B0 = __ldg(reinterpret_cast<const float4*>(src + 0 * W + cB));

    float4 hb0 = f4_hblur(A1, B1);   // HB[padded 0] = src row 1
    float4 hb1 = f4_hblur(A0, B0);   // HB[padded 1] = src row 0
    float4 hb2 = hb0;                // HB[padded 2] = src row 1
    float4 hb3;

    // Main loop: output oy consumes src row oy+2 from slot (oy&3), refills
    // that slot with src row oy+6. unroll 4 keeps the ring index static.
    #pragma unroll 4
    for (int oy = 0; oy < OH - 1; ++oy) {          // oy = 0..61
        const int s = oy & 3;
        hb3 = f4_hblur(pa[s], pb[s]);              // src row oy+2
        const int ny = oy + 6;
        if (ny < H) issue(ny, s);
        staged_store(oy, f4_vblur(hb0, hb1, hb2, hb3));
        hb0 = hb1; hb1 = hb2; hb2 = hb3;
    }

    // oy = 62: padded row 65 reflects to src row 62 (hot in cache — reload)
    {
        const float4 A = __ldg(reinterpret_cast<const float4*>(src + 62 * W + cA));
        const float4 B = __ldg(reinterpret_cast<const float4*>(src + 62 * W + cB));
        hb3 = f4_hblur(A, B);
        staged_store(OH - 1, f4_vblur(hb0, hb1, hb2, hb3));
    }
}

extern "C" void kernel_launch(void* const* d_in, const int* in_sizes, int n_in,
                              void* d_out, int out_size)
{
    const float* h = (const float*)d_in[0];
    float* out = (float*)d_out;

    const int n_img = 8 * 256;              // 2048 images of 64x512
    Blur_49976239456711_kernel<<<n_img, 128>>>(h, out);
}

// round 6
// speedup vs baseline: 1.6857x; 1.2678x over previous
#include <cuda_runtime.h>

// Depthwise separable 4x4 blur, filter [1,3,3,1] (x) [1,3,3,1] / 64.
// Input  (8, 256, 64, 512) fp32, W-pad circular(1), H-pad reflect(1).
// Output (8, 256, 63, 511) fp32.
//
// R6: R3's 4-deep register prefetch ring (read path, unchanged) + aligned
// STG.128 stores WITHOUT smem/barriers. Each thread computes 7 outputs
// o0..o6 (ox = 4t..4t+6); boundary values come from 2 predicated scalar
// loads (lanes 0/31) or warp shuffles. For row misalignment sh, the aligned
// quad at ox = a0+4t (a0=(4-sh)&3) is selected from o[a0..a0+3]. Thread 127
// writes the 3 per-row edge scalars (it owns them all, incl. circular wrap).

#define W   512
#define H   64
#define OW  511
#define OH  63

__global__ __launch_bounds__(128) void Blur_49976239456711_kernel(
    const float* __restrict__ in, float* __restrict__ out)
{
    const int t    = threadIdx.x;          // 0..127, owns src cols 4t..4t+3
    const int lane = t & 31;
    const int img  = blockIdx.x;           // 0..2047

    const float* __restrict__ src = in + (size_t)img * (H * W);
    const int imgbase = img * (OH * OW);   // flat float index of image output

    const int cA  = 4 * t;
    const int cB  = (4 * t + 4) & (W - 1); // wraps 512 -> 0 for t=127
    const int cm1 = (4 * t - 1) & (W - 1); // col 4t-1 (t=0 -> 511, circular)
    const int cp8 = (4 * t + 8) & (W - 1); // col 4t+8 (t>=126 wraps)

    const bool ldm1 = (lane == 0) || (t == 127);  // threads needing o0
    const bool ldp8 = (lane == 31);               // threads needing o6

    // ── 4-deep prefetch ring ──
    float4 pa[4], pb[4];
    float  pm1[4] = {0.f, 0.f, 0.f, 0.f};
    float  pp8[4] = {0.f, 0.f, 0.f, 0.f};

    auto issue = [&](int y, int s) {
        const float* r = src + y * W;
        pa[s] = __ldg(reinterpret_cast<const float4*>(r + cA));
        pb[s] = __ldg(reinterpret_cast<const float4*>(r + cB));
        if (ldm1) pm1[s] = __ldg(r + cm1);
        if (ldp8) pp8[s] = __ldg(r + cp8);
    };

    // h[j] = horizontal blur at ox = 4t+j (taps src cols ox-1..ox+2, w 1,3,3,1)
    auto hb7 = [](const float4& A, const float4& B, float m1, float p8, float* h) {
        h[0] = (m1  + A.z) + 3.f * (A.x + A.y);
        h[1] = (A.x + A.w) + 3.f * (A.y + A.z);
        h[2] = (A.y + B.x) + 3.f * (A.z + A.w);
        h[3] = (A.z + B.y) + 3.f * (A.w + B.x);
        h[4] = (A.w + B.z) + 3.f * (B.x + B.y);
        h[5] = (B.x + B.w) + 3.f * (B.y + B.z);
        h[6] = (B.y + p8)  + 3.f * (B.z + B.w);
    };

    // Store one output row from o[0..6]. Uniform per CTA (no divergence on a0).
    auto do_store = [&](int oy, const float* o) {
        const int rb = imgbase + oy * OW;          // flat row base
        const int a0 = (4 - (rb & 3)) & 3;         // first aligned ox in row
        float q0, q1, q2, q3;
        switch (a0) {
            case 0: {
                const float up = __shfl_up_sync(0xffffffffu, o[4], 1);
                q0 = (lane == 0) ? o[0] : up;      // ox 4t from t-1's o4 / own o0
                q1 = o[1]; q2 = o[2]; q3 = o[3];
            } break;
            case 1: q0 = o[1]; q1 = o[2]; q2 = o[3]; q3 = o[4]; break;
            case 2: q0 = o[2]; q1 = o[3]; q2 = o[4]; q3 = o[5]; break;
            default: {
                const float dn = __shfl_down_sync(0xffffffffu, o[2], 1);
                q0 = o[3]; q1 = o[4]; q2 = o[5];
                q3 = (lane == 31) ? o[6] : dn;     // ox 4t+6 from t+1's o2 / own o6
            } break;
        }
        if (t < 127) {
            *reinterpret_cast<float4*>(out + rb + a0 + 4 * t) =
                make_float4(q0, q1, q2, q3);
        } else {
            // 3 edge scalars; t=127 owns all of them (o4 = ox 0 circular,
            // o5 = ox 1, o6 = ox 2, o0..o2 = ox 508..510).
            switch (a0) {
                case 0:  out[rb + 508] = o[0]; out[rb + 509] = o[1]; out[rb + 510] = o[2]; break;
                case 1:  out[rb + 0]   = o[4]; out[rb + 509] = o[1]; out[rb + 510] = o[2]; break;
                case 2:  out[rb + 0]   = o[4]; out[rb + 1]   = o[5]; out[rb + 510] = o[2]; break;
                default: out[rb + 0]   = o[4]; out[rb + 1]   = o[5]; out[rb + 2]   = o[6]; break;
            }
        }
    };

    // Prologue: prefetch rows 2..5 (consumed at oy = 0..3).
    issue(2, 0); issue(3, 1); issue(4, 2); issue(5, 3);

    // Initial vertical window (reflect: padded 0 -> src 1, padded 1 -> src 0,
    // padded 2 -> src 1). Direct loads for src rows 0 and 1.
    float w0[7], w1[7], w2[7], h[7], o[7];
    {
        const float* r1 = src + 1 * W;
        const float4 A1 = __ldg(reinterpret_cast<const float4*>(r1 + cA));
        const float4 B1 = __ldg(reinterpret_cast<const float4*>(r1 + cB));
        const float  m1 = ldm1 ? __ldg(r1 + cm1) : 0.f;
        const float  p1 = ldp8 ? __ldg(r1 + cp8) : 0.f;
        hb7(A1, B1, m1, p1, w0);

        const float* r0 = src;
        const float4 A0 = __ldg(reinterpret_cast<const float4*>(r0 + cA));
        const float4 B0 = __ldg(reinterpret_cast<const float4*>(r0 + cB));
        const float  m0 = ldm1 ? __ldg(r0 + cm1) : 0.f;
        const float  p0 = ldp8 ? __ldg(r0 + cp8) : 0.f;
        hb7(A0, B0, m0, p0, w1);

        #pragma unroll
        for (int j = 0; j < 7; ++j) w2[j] = w0[j];
    }

    // Main loop: output oy consumes src row oy+2 from slot (oy&3), refills
    // that slot with src row oy+6. unroll 4 keeps ring indices static.
    #pragma unroll 4
    for (int oy = 0; oy < OH - 1; ++oy) {          // oy = 0..61
        const int s = oy & 3;
        hb7(pa[s], pb[s], pm1[s], pp8[s], h);      // src row oy+2
        const int ny = oy + 6;
        if (ny < H) issue(ny, s);

        #pragma unroll
        for (int j = 0; j < 7; ++j)
            o[j] = ((w0[j] + h[j]) + 3.f * (w1[j] + w2[j])) * (1.f / 64.f);
        do_store(oy, o);

        #pragma unroll
        for (int j = 0; j < 7; ++j) { w0[j] = w1[j]; w1[j] = w2[j]; w2[j] = h[j]; }
    }

    // oy = 62: padded rows 62,63,64,65 -> src 61,62,63,62 = (w0, w1, w2, w1).
    #pragma unroll
    for (int j = 0; j < 7; ++j)
        o[j] = ((w0[j] + w1[j]) + 3.f * (w1[j] + w2[j])) * (1.f / 64.f);
    do_store(OH - 1, o);
}

extern "C" void kernel_launch(void* const* d_in, const int* in_sizes, int n_in,
                              void* d_out, int out_size)
{
    const float* h = (const float*)d_in[0];
    float* out = (float*)d_out;

    const int n_img = 8 * 256;              // 2048 images of 64x512
    Blur_49976239456711_kernel<<<n_img, 128>>>(h, out);
}